// round 1
// baseline (speedup 1.0000x reference)
#include <cuda_runtime.h>
#include <cstdint>

// Problem constants (fixed by the reference)
#define NB  32
#define MP  30
#define KJ  17
#define KHW (17 * 256 * 256)   // 1114112
#define MK  (MP * KJ)          // 510

__global__ void ae_loss_kernel(const float* __restrict__ tags,
                               const int*   __restrict__ joints,
                               float*       __restrict__ out) {
    const int n = blockIdx.x;
    const float* tg = tags + (size_t)n * KHW;
    const int*   jt = joints + (size_t)n * MK * 2;

    __shared__ float s_t[MK];   // gathered tag values
    __shared__ float s_v[MK];   // visibility (0/1)
    __shared__ float s_mu[MP];
    __shared__ float s_pv[MP];

    const int t = threadIdx.x;

    // Phase 1: one thread per (person, joint) — gather tag + visibility.
    if (t < MK) {
        int2 j = reinterpret_cast<const int2*>(jt)[t];  // (idx, vis)
        float v = (j.y > 0) ? 1.0f : 0.0f;
        s_t[t] = __ldg(tg + j.x);
        s_v[t] = v;
    }
    __syncthreads();

    // Phase 2: one thread per person (threads 0..29, all in warp 0).
    float mu = 0.0f, pvf = 0.0f, pull_pp = 0.0f;
    if (t < MP) {
        float cnt = 0.0f, stv = 0.0f;
        #pragma unroll
        for (int k = 0; k < KJ; k++) {
            float v = s_v[t * KJ + k];
            cnt += v;
            stv += v * s_t[t * KJ + k];
        }
        float cs = fmaxf(cnt, 1.0f);
        mu = stv / cs;
        float acc = 0.0f;
        #pragma unroll
        for (int k = 0; k < KJ; k++) {
            float d = s_t[t * KJ + k] - mu;
            acc += s_v[t * KJ + k] * d * d;
        }
        pvf = (cnt > 0.0f) ? 1.0f : 0.0f;
        pull_pp = pvf * (acc / cs);
        s_mu[t] = mu;
        s_pv[t] = pvf;
    }
    __syncwarp();

    // Phase 3: push — pairwise exp(-(mu_i - mu_j)^2) over valid persons.
    float psum = 0.0f;
    if (t < MP && pvf > 0.0f) {
        #pragma unroll
        for (int j = 0; j < MP; j++) {
            float d = mu - s_mu[j];
            psum += s_pv[j] * expf(-d * d);
        }
    }

    // Phase 4: warp-0 reduction of pull, n (valid person count), push sums.
    if (t < 32) {
        float pull = (t < MP) ? pull_pp : 0.0f;
        float nn   = (t < MP) ? pvf     : 0.0f;
        float ps   = (t < MP) ? psum    : 0.0f;
        #pragma unroll
        for (int o = 16; o > 0; o >>= 1) {
            pull += __shfl_down_sync(0xffffffffu, pull, o);
            nn   += __shfl_down_sync(0xffffffffu, nn,   o);
            ps   += __shfl_down_sync(0xffffffffu, ps,   o);
        }
        if (t == 0) {
            float push  = ps - nn;                       // subtract diagonal
            float denom = fmaxf((nn - 1.0f) * nn, 1.0f);
            out[n]      = push / denom * 0.5f;           // pushes [0..31]
            out[NB + n] = pull / fmaxf(nn, 1.0f);        // pulls  [32..63]
        }
    }
}

extern "C" void kernel_launch(void* const* d_in, const int* in_sizes, int n_in,
                              void* d_out, int out_size) {
    const float* tags   = (const float*)d_in[0];  // [N, KHW, 1] float32
    const int*   joints = (const int*)d_in[1];    // [N, M, K, 2] int32
    float* out = (float*)d_out;                   // [2*N] = pushes ++ pulls
    ae_loss_kernel<<<NB, 512>>>(tags, joints, out);
}

// round 2
// speedup vs baseline: 1.0370x; 1.0370x over previous
#include <cuda_runtime.h>
#include <cstdint>

// Problem constants (fixed by the reference)
#define NB  32
#define MP  30
#define KJ  17
#define KHW (17 * 256 * 256)   // 1114112
#define MK  (MP * KJ)          // 510

// Warp-per-person layout: 30 warps (960 threads), one CTA per batch image.
__global__ __launch_bounds__(MP * 32, 1)
void ae_loss_kernel(const float* __restrict__ tags,
                    const int*   __restrict__ joints,
                    float*       __restrict__ out) {
    const int n = blockIdx.x;
    const float* tg = tags   + (size_t)n * KHW;
    const int*   jt = joints + (size_t)n * MK * 2;

    const int wid  = threadIdx.x >> 5;   // person index 0..29
    const int lane = threadIdx.x & 31;

    __shared__ float s_mu[MP];
    __shared__ float s_pv[MP];
    __shared__ float s_psum[MP];
    __shared__ float s_pull[MP];

    // ---- Phase A: gather + per-person stats (register/shuffle only) ----
    float t = 0.0f, v = 0.0f;
    if (lane < KJ) {
        int2 j = reinterpret_cast<const int2*>(jt)[wid * KJ + lane];
        v = (j.y > 0) ? 1.0f : 0.0f;
        t = v * __ldg(tg + j.x);         // masked tag (v=0 -> 0)
    }
    // warp butterfly reduce: cnt, sum(v*t), sum(v*t^2)
    float cnt = v, s1 = t, s2 = t * t;
    #pragma unroll
    for (int o = 16; o > 0; o >>= 1) {
        cnt += __shfl_xor_sync(0xffffffffu, cnt, o);
        s1  += __shfl_xor_sync(0xffffffffu, s1,  o);
        s2  += __shfl_xor_sync(0xffffffffu, s2,  o);
    }
    float cs   = fmaxf(cnt, 1.0f);
    float rcs  = __fdividef(1.0f, cs);
    float mu   = s1 * rcs;
    float pvf  = (cnt > 0.0f) ? 1.0f : 0.0f;
    // sum v*(t-mu)^2 = s2 - cnt*mu^2  (valid since s1 = cnt*mu)
    float pull = pvf * fmaxf(s2 - cnt * mu * mu, 0.0f) * rcs;

    if (lane == 0) {
        s_mu[wid]   = mu;
        s_pv[wid]   = pvf;
        s_pull[wid] = pull;
    }
    __syncthreads();

    // ---- Phase B: push pairs — warp i, lane j handles pair (i, j) ----
    float term = 0.0f;
    if (lane < MP) {
        float d = mu - s_mu[lane];
        term = pvf * s_pv[lane] * __expf(-d * d);
    }
    #pragma unroll
    for (int o = 16; o > 0; o >>= 1)
        term += __shfl_xor_sync(0xffffffffu, term, o);
    if (lane == 0) s_psum[wid] = term;
    __syncthreads();

    // ---- Phase C: warp 0 reduces the 30 per-person values ----
    if (wid == 0) {
        float pl = 0.0f, nn = 0.0f, ps = 0.0f;
        if (lane < MP) {
            pl = s_pull[lane];
            nn = s_pv[lane];
            ps = s_psum[lane];
        }
        #pragma unroll
        for (int o = 16; o > 0; o >>= 1) {
            pl += __shfl_xor_sync(0xffffffffu, pl, o);
            nn += __shfl_xor_sync(0xffffffffu, nn, o);
            ps += __shfl_xor_sync(0xffffffffu, ps, o);
        }
        if (lane == 0) {
            float push  = ps - nn;                       // remove diagonal
            float denom = fmaxf((nn - 1.0f) * nn, 1.0f);
            out[n]      = push * __fdividef(0.5f, denom);    // pushes [0..31]
            out[NB + n] = pl * __fdividef(1.0f, fmaxf(nn, 1.0f)); // pulls
        }
    }
}

extern "C" void kernel_launch(void* const* d_in, const int* in_sizes, int n_in,
                              void* d_out, int out_size) {
    const float* tags   = (const float*)d_in[0];  // [N, KHW, 1] float32
    const int*   joints = (const int*)d_in[1];    // [N, M, K, 2] int32
    float* out = (float*)d_out;                   // [2*N] = pushes ++ pulls
    ae_loss_kernel<<<NB, MP * 32>>>(tags, joints, out);
}

// round 3
// speedup vs baseline: 1.0769x; 1.0385x over previous
#include <cuda_runtime.h>
#include <cstdint>

// Problem constants (fixed by the reference)
#define NB  32
#define MP  30
#define KJ  17
#define KHW (17 * 256 * 256)   // 1114112
#define MK  (MP * KJ)          // 510

// One warp per batch image; lane p owns person p. No smem, no block barriers.
__global__ __launch_bounds__(32, 1)
void ae_loss_kernel(const float* __restrict__ tags,
                    const int*   __restrict__ joints,
                    float*       __restrict__ out) {
    const int n = blockIdx.x;
    const float* tg = tags + (size_t)n * KHW;
    const int2*  jt = reinterpret_cast<const int2*>(joints) + (size_t)n * MK;

    const int lane = threadIdx.x;

    float mu = 0.0f, pvf = 0.0f, pull = 0.0f;

    if (lane < MP) {
        // Load 17 joints (idx, vis) for this person — independent LDGs.
        int2 j[KJ];
        #pragma unroll
        for (int k = 0; k < KJ; k++)
            j[k] = __ldg(&jt[lane * KJ + k]);

        // Gather 17 tags — all independent, overlapped across the warp.
        float t[KJ], v[KJ];
        #pragma unroll
        for (int k = 0; k < KJ; k++) {
            v[k] = (j[k].y > 0) ? 1.0f : 0.0f;
            t[k] = v[k] * __ldg(tg + j[k].x);   // masked tag
        }

        float cnt = 0.0f, s1 = 0.0f, s2 = 0.0f;
        #pragma unroll
        for (int k = 0; k < KJ; k++) {
            cnt += v[k];
            s1  += t[k];
            s2  += t[k] * t[k];
        }
        float cs  = fmaxf(cnt, 1.0f);
        float rcs = __fdividef(1.0f, cs);
        mu  = s1 * rcs;
        pvf = (cnt > 0.0f) ? 1.0f : 0.0f;
        // sum v*(t-mu)^2 = s2 - cnt*mu^2   (since s1 = cnt*mu for valid persons)
        pull = pvf * fmaxf(s2 - cnt * mu * mu, 0.0f) * rcs;
    }

    // Push: lane i accumulates sum_j pv_j * exp(-(mu_i-mu_j)^2) via shuffles.
    float psum = 0.0f;
    #pragma unroll
    for (int jj = 0; jj < MP; jj++) {
        float muj = __shfl_sync(0xffffffffu, mu,  jj);
        float pvj = __shfl_sync(0xffffffffu, pvf, jj);
        float d = mu - muj;
        psum += pvj * __expf(-d * d);
    }
    psum *= pvf;   // zero out invalid persons / lanes 30,31

    // Warp butterfly reduce: pull, n (valid persons), push sum.
    float nn = pvf;
    #pragma unroll
    for (int o = 16; o > 0; o >>= 1) {
        pull += __shfl_xor_sync(0xffffffffu, pull, o);
        nn   += __shfl_xor_sync(0xffffffffu, nn,   o);
        psum += __shfl_xor_sync(0xffffffffu, psum, o);
    }

    if (lane == 0) {
        float push  = psum - nn;                         // remove diagonal
        float denom = fmaxf((nn - 1.0f) * nn, 1.0f);
        out[n]      = push * __fdividef(0.5f, denom);    // pushes [0..31]
        out[NB + n] = pull * __fdividef(1.0f, fmaxf(nn, 1.0f)); // pulls [32..63]
    }
}

extern "C" void kernel_launch(void* const* d_in, const int* in_sizes, int n_in,
                              void* d_out, int out_size) {
    const float* tags   = (const float*)d_in[0];  // [N, KHW, 1] float32
    const int*   joints = (const int*)d_in[1];    // [N, M, K, 2] int32
    float* out = (float*)d_out;                   // [2*N] = pushes ++ pulls
    ae_loss_kernel<<<NB, 32>>>(tags, joints, out);
}

// round 4
// speedup vs baseline: 1.0821x; 1.0048x over previous
#include <cuda_runtime.h>
#include <cstdint>

// Problem constants (fixed by the reference)
#define NB  32
#define MP  30
#define KJ  17
#define KHW (17 * 256 * 256)   // 1114112
#define MK  (MP * KJ)          // 510  joints per image
#define NI4 (MK * 2 / 4)       // 255  int4 words of joints per image

// One warp per batch image. Coalesced joints load; gather from registers;
// smem only for the (v, v*t) redistribution; rotation push loop.
__global__ __launch_bounds__(32, 1)
void ae_loss_kernel(const float* __restrict__ tags,
                    const int*   __restrict__ joints,
                    float*       __restrict__ out) {
    const int n = blockIdx.x;
    const float* tg = tags + (size_t)n * KHW;
    const int4*  j4 = reinterpret_cast<const int4*>(joints + (size_t)n * MK * 2);

    const int lane = threadIdx.x;

    __shared__ float2 s_pair[MK];   // (v, v*t) per joint

    // ---- Phase A: coalesced joints load, gather own joints, scatter to smem ----
    #pragma unroll
    for (int w = 0; w < 8; w++) {
        int m = lane + 32 * w;                  // int4 index = covers joints 2m, 2m+1
        if (m < NI4) {
            int4 q = __ldg(&j4[m]);
            float v0 = (q.y > 0) ? 1.0f : 0.0f;
            float v1 = (q.w > 0) ? 1.0f : 0.0f;
            float t0 = 0.0f, t1 = 0.0f;
            if (q.y > 0) t0 = __ldg(tg + q.x);  // predicated gather (skip invisible)
            if (q.w > 0) t1 = __ldg(tg + q.z);
            s_pair[2 * m]     = make_float2(v0, t0);
            s_pair[2 * m + 1] = make_float2(v1, t1);
        }
    }
    __syncwarp();

    // ---- Phase B: per-person stats (lane p owns person p) ----
    float mu = 0.0f, pvf = 0.0f, pull = 0.0f;
    if (lane < MP) {
        float cnt = 0.0f, s1 = 0.0f, s2 = 0.0f;
        #pragma unroll
        for (int k = 0; k < KJ; k++) {
            float2 pr = s_pair[lane * KJ + k];
            cnt += pr.x;
            s1  += pr.y;
            s2  += pr.y * pr.y;   // (v*t)^2 == v*t^2 since v in {0,1}
        }
        float cs  = fmaxf(cnt, 1.0f);
        float rcs = __fdividef(1.0f, cs);
        mu  = s1 * rcs;
        pvf = (cnt > 0.0f) ? 1.0f : 0.0f;
        pull = pvf * fmaxf(s2 - cnt * mu * mu, 0.0f) * rcs;
    }

    // ---- Phase C: push via rotation (off-diagonal only, symmetry-halved) ----
    // ordered pairs = offsets 1..29; term(off) == term(30-off) pairwise, so
    // sum = 2 * sum(off=1..14) + sum(off=15).  Diagonal never appears.
    float psum2 = 0.0f, psum1 = 0.0f;
    #pragma unroll
    for (int off = 1; off <= 15; off++) {
        int src = lane + off;
        if (src >= MP) src -= MP;
        float muj = __shfl_sync(0xffffffffu, mu,  src);
        float pvj = __shfl_sync(0xffffffffu, pvf, src);
        float d = mu - muj;
        float term = pvj * __expf(-d * d);
        if (off < 15) psum2 += term; else psum1 = term;
    }
    float psum = pvf * (2.0f * psum2 + psum1);  // mask invalid persons/lanes

    // ---- Phase D: warp butterfly reduce (pull, n, push) ----
    float nn = pvf;
    #pragma unroll
    for (int o = 16; o > 0; o >>= 1) {
        pull += __shfl_xor_sync(0xffffffffu, pull, o);
        nn   += __shfl_xor_sync(0xffffffffu, nn,   o);
        psum += __shfl_xor_sync(0xffffffffu, psum, o);
    }

    if (lane == 0) {
        float denom = fmaxf((nn - 1.0f) * nn, 1.0f);
        out[n]      = psum * __fdividef(0.5f, denom);          // pushes [0..31]
        out[NB + n] = pull * __fdividef(1.0f, fmaxf(nn, 1.0f)); // pulls [32..63]
    }
}

extern "C" void kernel_launch(void* const* d_in, const int* in_sizes, int n_in,
                              void* d_out, int out_size) {
    const float* tags   = (const float*)d_in[0];  // [N, KHW, 1] float32
    const int*   joints = (const int*)d_in[1];    // [N, M, K, 2] int32
    float* out = (float*)d_out;                   // [2*N] = pushes ++ pulls
    ae_loss_kernel<<<NB, 32>>>(tags, joints, out);
}